// round 14
// baseline (speedup 1.0000x reference)
#include <cuda_runtime.h>
#include <cuda_bf16.h>
#include <cstdint>

#define N_NODES 50000
#define N_EDGES 300000
#define HID 256
#define ZDIM 128
#define NLAYERS 3
#define NGRAPHS 16
#define EPS 1e-5f

// ---------------- device scratch (no allocations allowed) ----------------
__device__ float g_deg[N_NODES];
__device__ float g_dinv[N_NODES];
__device__ int   g_off[N_NODES + 1];
__device__ int   g_cursor[N_NODES];
__device__ int   g_csrc[N_EDGES];
__device__ float g_cw[N_EDGES];
__device__ unsigned g_h[N_NODES * 128];    // h as bf16x2: 128 uints per row (256 ch)
__device__ unsigned g_xh[N_NODES * 128];   // bf16x2 hi
__device__ unsigned g_xl[N_NODES * 128];   // bf16x2 lo
__device__ unsigned g_yh[N_NODES * 128];
__device__ unsigned g_yl[N_NODES * 128];
__device__ unsigned g_wh[NLAYERS * 256 * 128];  // W^T split hi: [l][n][kpair]
__device__ unsigned g_wl[NLAYERS * 256 * 128];
__device__ float g_pool[NGRAPHS * HID];
__device__ float g_cnt[NGRAPHS];
__device__ int   g_bsum[64];

// ---------------- bf16 helpers ----------------
__device__ __forceinline__ unsigned pack_hi2(float x, float y, float& lx, float& ly) {
    __nv_bfloat162 h = __floats2bfloat162_rn(x, y);
    lx = x - __bfloat162float(h.x);
    ly = y - __bfloat162float(h.y);
    unsigned u;
    *reinterpret_cast<__nv_bfloat162*>(&u) = h;
    return u;
}
__device__ __forceinline__ unsigned pack2(float x, float y) {
    __nv_bfloat162 h = __floats2bfloat162_rn(x, y);
    unsigned u;
    *reinterpret_cast<__nv_bfloat162*>(&u) = h;
    return u;
}
__device__ __forceinline__ float2 upkb(unsigned u) {
    return __bfloat1622float2(*reinterpret_cast<__nv_bfloat162*>(&u));
}
__device__ __forceinline__ float2 upk2(unsigned uh, unsigned ul) {
    float2 a = upkb(uh), b = upkb(ul);
    return make_float2(a.x + b.x, a.y + b.y);
}

__device__ __forceinline__ uint32_t smem_u32(const void* p) {
    uint32_t a;
    asm("{ .reg .u64 t; cvta.to.shared.u64 t, %1; cvt.u32.u64 %0, t; }" : "=r"(a) : "l"(p));
    return a;
}

// ---------------- warp GroupNorm helper ----------------
__device__ __forceinline__ void warp_gn(float s1, float s2, float& mu, float& inv) {
    #pragma unroll
    for (int s = 16; s > 0; s >>= 1) {
        s1 += __shfl_xor_sync(~0u, s1, s);
        s2 += __shfl_xor_sync(~0u, s2, s);
    }
    mu = s1 * (1.0f / HID);
    float var = s2 * (1.0f / HID) - mu * mu;
    inv = rsqrtf(fmaxf(var, 0.0f) + EPS);
}

// ------- merged setup: inproj | wsplit | deg/cursor init | pool zero -------
#define NB_INPROJ (N_NODES / 8)
#define NB_WSPLIT ((NLAYERS * 256 * 128) / 256)
#define NB_INIT   ((N_NODES + 255) / 256)
#define NB_SETUP  (NB_INPROJ + NB_WSPLIT + NB_INIT + 1)

__global__ __launch_bounds__(256) void k_setup(
        const float* __restrict__ pos, const float* __restrict__ W,
        const float* __restrict__ b, const float* __restrict__ g,
        const float* __restrict__ be,
        unsigned* __restrict__ oh, unsigned* __restrict__ ol,
        const float* __restrict__ convW, unsigned* __restrict__ Bh,
        unsigned* __restrict__ Bl,
        float* __restrict__ deg, int* __restrict__ cursor,
        float* __restrict__ pool, float* __restrict__ cnt) {
    int blk = blockIdx.x;
    if (blk < NB_INPROJ) {
        // ---- input projection: warp per node ----
        int lane = threadIdx.x & 31;
        int i = blk * 8 + (threadIdx.x >> 5);
        float px = pos[i * 3 + 0], py = pos[i * 3 + 1], pz = pos[i * 3 + 2];
        const float4* W0 = (const float4*)W;
        const float4* W1 = (const float4*)(W + HID);
        const float4* W2 = (const float4*)(W + 2 * HID);
        const float4* b4 = (const float4*)b;
        float4 v[2];
        float s1 = 0.0f, s2 = 0.0f;
        #pragma unroll
        for (int q = 0; q < 2; q++) {
            int c4 = lane + q * 32;
            float4 w0 = W0[c4], w1 = W1[c4], w2 = W2[c4], bb = b4[c4];
            float4 r;
            r.x = fmaxf(fmaf(px, w0.x, fmaf(py, w1.x, fmaf(pz, w2.x, bb.x))), 0.0f);
            r.y = fmaxf(fmaf(px, w0.y, fmaf(py, w1.y, fmaf(pz, w2.y, bb.y))), 0.0f);
            r.z = fmaxf(fmaf(px, w0.z, fmaf(py, w1.z, fmaf(pz, w2.z, bb.z))), 0.0f);
            r.w = fmaxf(fmaf(px, w0.w, fmaf(py, w1.w, fmaf(pz, w2.w, bb.w))), 0.0f);
            s1 += r.x + r.y + r.z + r.w;
            s2 += r.x * r.x + r.y * r.y + r.z * r.z + r.w * r.w;
            v[q] = r;
        }
        float mu, inv;
        warp_gn(s1, s2, mu, inv);
        const float4* g4 = (const float4*)g;
        const float4* be4 = (const float4*)be;
        unsigned* ohp = oh + (size_t)i * 128;
        unsigned* olp = ol + (size_t)i * 128;
        #pragma unroll
        for (int q = 0; q < 2; q++) {
            int c4 = lane + q * 32;
            float4 gg = g4[c4], ee = be4[c4], r = v[q];
            r.x = (r.x - mu) * inv * gg.x + ee.x;
            r.y = (r.y - mu) * inv * gg.y + ee.y;
            r.z = (r.z - mu) * inv * gg.z + ee.z;
            r.w = (r.w - mu) * inv * gg.w + ee.w;
            float lx, ly;
            ohp[c4 * 2]     = pack_hi2(r.x, r.y, lx, ly);
            olp[c4 * 2]     = pack2(lx, ly);
            ohp[c4 * 2 + 1] = pack_hi2(r.z, r.w, lx, ly);
            olp[c4 * 2 + 1] = pack2(lx, ly);
        }
    } else if (blk < NB_INPROJ + NB_WSPLIT) {
        // ---- weight transpose + split ----
        int idx = (blk - NB_INPROJ) * 256 + threadIdx.x;
        int ln = idx >> 7, p = idx & 127;
        int l = ln >> 8, n = ln & 255;
        const float* Wl = convW + (size_t)l * 65536;
        float w0 = Wl[(size_t)(2 * p) * 256 + n];
        float w1 = Wl[(size_t)(2 * p + 1) * 256 + n];
        float l0, l1;
        unsigned hi = pack_hi2(w0, w1, l0, l1);
        Bh[(size_t)ln * 128 + p] = hi;
        Bl[(size_t)ln * 128 + p] = pack2(l0, l1);
    } else if (blk < NB_INPROJ + NB_WSPLIT + NB_INIT) {
        // ---- deg/cursor init ----
        int i = (blk - NB_INPROJ - NB_WSPLIT) * 256 + threadIdx.x;
        if (i < N_NODES) { deg[i] = 1.0f; cursor[i] = 0; }
    } else {
        // ---- pool/cnt zero ----
        for (int k = threadIdx.x; k < NGRAPHS * HID; k += 256) pool[k] = 0.0f;
        if (threadIdx.x < NGRAPHS) cnt[threadIdx.x] = 0.0f;
    }
}

// ---------------- degree / CSR build ----------------
__global__ void k_deg(const int* __restrict__ dst, float* deg) {
    int e = blockIdx.x * blockDim.x + threadIdx.x;
    if (e < N_EDGES) atomicAdd(&deg[dst[e]], 1.0f);
}

#define SCAN_B 1024
#define SCAN_NB ((N_NODES + SCAN_B - 1) / SCAN_B)

__global__ void k_bsum2(const float* __restrict__ deg, float* __restrict__ dinv,
                        int* bsum) {
    __shared__ int wsum[32];
    int t = threadIdx.x;
    int i = blockIdx.x * SCAN_B + t;
    int v = 0;
    if (i < N_NODES) {
        float d = deg[i];
        dinv[i] = rsqrtf(d);
        v = (int)d - 1;
    }
    #pragma unroll
    for (int s = 16; s > 0; s >>= 1) v += __shfl_xor_sync(~0u, v, s);
    if ((t & 31) == 0) wsum[t >> 5] = v;
    __syncthreads();
    if (t < 32) {
        int x = wsum[t];
        #pragma unroll
        for (int s = 16; s > 0; s >>= 1) x += __shfl_xor_sync(~0u, x, s);
        if (t == 0) bsum[blockIdx.x] = x;
    }
}

// scan with inlined block-prefix
__global__ void k_scan2(const float* __restrict__ deg, const int* __restrict__ bsum,
                        int* off) {
    __shared__ int wsum[32];
    __shared__ int bpre_s;
    int t = threadIdx.x, lane = t & 31, w = t >> 5;
    if (t < 64) {
        int v = (t < blockIdx.x && t < SCAN_NB) ? bsum[t] : 0;
        #pragma unroll
        for (int s = 16; s > 0; s >>= 1) v += __shfl_xor_sync(~0u, v, s);
        if (t == 0) wsum[30] = v;
        if (t == 32) wsum[31] = v;
    }
    __syncthreads();
    if (t == 0) bpre_s = wsum[30] + wsum[31];
    __syncthreads();

    int i = blockIdx.x * SCAN_B + t;
    int v = (i < N_NODES) ? ((int)deg[i] - 1) : 0;
    int x = v;
    #pragma unroll
    for (int s = 1; s < 32; s <<= 1) {
        int n = __shfl_up_sync(~0u, x, s);
        if (lane >= s) x += n;
    }
    if (lane == 31) wsum[w] = x;
    __syncthreads();
    if (w == 0) {
        int y = wsum[lane];
        #pragma unroll
        for (int s = 1; s < 32; s <<= 1) {
            int n = __shfl_up_sync(~0u, y, s);
            if (lane >= s) y += n;
        }
        wsum[lane] = y;
    }
    __syncthreads();
    int incl = x + ((w > 0) ? wsum[w - 1] : 0);
    if (i < N_NODES) off[i + 1] = bpre_s + incl;
    if (i == 0) off[0] = 0;
}

__global__ void k_csr(const int* __restrict__ src, const int* __restrict__ dst,
                      const float* __restrict__ dinv, const int* __restrict__ off,
                      int* cursor, int* csrc, float* cw) {
    int e = blockIdx.x * blockDim.x + threadIdx.x;
    if (e >= N_EDGES) return;
    int s = src[e], d = dst[e];
    int p = atomicAdd(&cursor[d], 1);
    int idx = off[d] + p;
    csrc[idx] = s;
    cw[idx] = dinv[s] * dinv[d];
}

// ---------------- bf16x3 MMA GEMM: cp.async 3-stage pipeline + ldmatrix ----------------
#define MMA_BF16(d0, d1, d2, d3, a0, a1, a2, a3, b0, b1)                      \
    asm volatile(                                                             \
        "mma.sync.aligned.m16n8k16.row.col.f32.bf16.bf16.f32 "               \
        "{%0,%1,%2,%3}, {%4,%5,%6,%7}, {%8,%9}, {%0,%1,%2,%3};\n"            \
        : "+f"(d0), "+f"(d1), "+f"(d2), "+f"(d3)                              \
        : "r"(a0), "r"(a1), "r"(a2), "r"(a3), "r"(b0), "r"(b1))

#define LDSM_X4(r0, r1, r2, r3, addr)                                         \
    asm volatile("ldmatrix.sync.aligned.m8n8.x4.shared.b16 {%0,%1,%2,%3}, [%4];" \
        : "=r"(r0), "=r"(r1), "=r"(r2), "=r"(r3) : "r"(addr))

#define CP16(dst, src, ssz)                                                   \
    asm volatile("cp.async.cg.shared.global [%0], [%1], 16, %2;"             \
        :: "r"(dst), "l"(src), "r"(ssz))
#define CP_COMMIT() asm volatile("cp.async.commit_group;" ::: "memory")
#define CP_WAIT1() asm volatile("cp.async.wait_group 1;" ::: "memory")
#define CP_WAIT0() asm volatile("cp.async.wait_group 0;" ::: "memory")

#define ARR_B 6144
#define STG_B 24576
#define GSMEM (3 * STG_B)

__global__ void __launch_bounds__(256, 2) k_gemm_bf(
        const unsigned* __restrict__ Agh, const unsigned* __restrict__ Agl,
        const unsigned* __restrict__ Bgh, const unsigned* __restrict__ Bgl,
        unsigned* __restrict__ C, int M) {
    extern __shared__ unsigned smg[];
    uint32_t sb = smem_u32(smg);
    int t = threadIdx.x;
    int lane = t & 31, wid = t >> 5;
    int wm = (wid >> 2) * 64;
    int wn = (wid & 3) * 32;
    int g = lane >> 2, tig = lane & 3;
    int m0 = blockIdx.x * 128, n0 = blockIdx.y * 128;

    float acc[4][4][4];
    #pragma unroll
    for (int mt = 0; mt < 4; mt++)
        #pragma unroll
        for (int nt = 0; nt < 4; nt++)
            #pragma unroll
            for (int r = 0; r < 4; r++) acc[mt][nt][r] = 0.0f;

    int rr = t >> 1, q = t & 1;
    uint32_t a_ok = ((m0 + rr) < M) ? 16u : 0u;
    const char* pAh = (const char*)(Agh + (size_t)(m0 + rr) * 128) + q * 16;
    const char* pAl = (const char*)(Agl + (size_t)(m0 + rr) * 128) + q * 16;
    const char* pBh = (const char*)(Bgh + (size_t)(n0 + rr) * 128) + q * 16;
    const char* pBl = (const char*)(Bgl + (size_t)(n0 + rr) * 128) + q * 16;
    uint32_t sdst = sb + rr * 48 + q * 16;

    uint32_t a_off[4];
    #pragma unroll
    for (int mt = 0; mt < 4; mt++) {
        int row = wm + mt * 16 + (lane & 7) + ((lane >> 3) & 1) * 8;
        a_off[mt] = row * 48 + (lane >> 4) * 16;
    }
    uint32_t b_off[2];
    #pragma unroll
    for (int p = 0; p < 2; p++) {
        int nrow = wn + p * 16 + (lane & 7) + ((lane >> 4) & 1) * 8;
        b_off[p] = nrow * 48 + ((lane >> 3) & 1) * 16;
    }

    #define ISSUE(kt, stg) do {                                               \
        uint32_t d = sdst + (stg) * STG_B;                                    \
        int ko = (kt) * 32;                                                   \
        CP16(d,               pAh + ko, a_ok);                                \
        CP16(d + ARR_B,       pAl + ko, a_ok);                                \
        CP16(d + 2 * ARR_B,   pBh + ko, 16u);                                 \
        CP16(d + 3 * ARR_B,   pBl + ko, 16u);                                 \
        CP_COMMIT();                                                          \
    } while (0)

    #define COMPUTE(so) do {                                                  \
        unsigned afh[4][4], afl[4][4], bfh[4][2], bfl[4][2];                  \
        uint32_t ahb = sb + (so), alb = ahb + ARR_B;                          \
        uint32_t bhb = ahb + 2 * ARR_B, blb = ahb + 3 * ARR_B;                \
        _Pragma("unroll")                                                     \
        for (int mt = 0; mt < 4; mt++) {                                      \
            LDSM_X4(afh[mt][0], afh[mt][1], afh[mt][2], afh[mt][3], ahb + a_off[mt]); \
            LDSM_X4(afl[mt][0], afl[mt][1], afl[mt][2], afl[mt][3], alb + a_off[mt]); \
        }                                                                     \
        _Pragma("unroll")                                                     \
        for (int p = 0; p < 2; p++) {                                         \
            LDSM_X4(bfh[2*p][0], bfh[2*p][1], bfh[2*p+1][0], bfh[2*p+1][1], bhb + b_off[p]); \
            LDSM_X4(bfl[2*p][0], bfl[2*p][1], bfl[2*p+1][0], bfl[2*p+1][1], blb + b_off[p]); \
        }                                                                     \
        _Pragma("unroll")                                                     \
        for (int mt = 0; mt < 4; mt++)                                        \
            _Pragma("unroll")                                                 \
            for (int nt = 0; nt < 4; nt++) {                                  \
                MMA_BF16(acc[mt][nt][0], acc[mt][nt][1], acc[mt][nt][2], acc[mt][nt][3], \
                         afh[mt][0], afh[mt][1], afh[mt][2], afh[mt][3],      \
                         bfh[nt][0], bfh[nt][1]);                             \
                MMA_BF16(acc[mt][nt][0], acc[mt][nt][1], acc[mt][nt][2], acc[mt][nt][3], \
                         afh[mt][0], afh[mt][1], afh[mt][2], afh[mt][3],      \
                         bfl[nt][0], bfl[nt][1]);                             \
                MMA_BF16(acc[mt][nt][0], acc[mt][nt][1], acc[mt][nt][2], acc[mt][nt][3], \
                         afl[mt][0], afl[mt][1], afl[mt][2], afl[mt][3],      \
                         bfh[nt][0], bfh[nt][1]);                             \
            }                                                                 \
    } while (0)

    ISSUE(0, 0);
    ISSUE(1, 1);

    int cur = 0;
    uint32_t curo = 0;
    #pragma unroll 1
    for (int kt = 0; kt < 15; kt++) {
        CP_WAIT1();
        __syncthreads();
        if (kt < 14) {
            int stg = cur + 2; if (stg >= 3) stg -= 3;
            ISSUE(kt + 2, stg);
        }
        COMPUTE(curo);
        cur++; if (cur == 3) cur = 0;
        curo = cur * STG_B;
    }
    CP_WAIT0();
    __syncthreads();
    COMPUTE(curo);

    #pragma unroll
    for (int mt = 0; mt < 4; mt++) {
        #pragma unroll
        for (int nt = 0; nt < 4; nt++) {
            int r0 = m0 + wm + mt * 16 + g;
            int ci = (n0 + wn + nt * 8 + tig * 2) >> 1;
            if (r0 < M)
                C[(size_t)r0 * 128 + ci] = pack2(acc[mt][nt][0], acc[mt][nt][1]);
            if (r0 + 8 < M)
                C[(size_t)(r0 + 8) * 128 + ci] = pack2(acc[mt][nt][2], acc[mt][nt][3]);
        }
    }
    #undef ISSUE
    #undef COMPUTE
}

// ---- aggregate: warp per node, bf16 h gather (1 LDG/edge), x4 unroll ----
#define EDGE_FMA8(u, wj) do {                                                 \
    float2 f0 = upkb(u.x), f1 = upkb(u.y), f2 = upkb(u.z), f3 = upkb(u.w);    \
    a[0] = fmaf(f0.x, wj, a[0]); a[1] = fmaf(f0.y, wj, a[1]);                 \
    a[2] = fmaf(f1.x, wj, a[2]); a[3] = fmaf(f1.y, wj, a[3]);                 \
    a[4] = fmaf(f2.x, wj, a[4]); a[5] = fmaf(f2.y, wj, a[5]);                 \
    a[6] = fmaf(f3.x, wj, a[6]); a[7] = fmaf(f3.y, wj, a[7]);                 \
} while (0)

__global__ __launch_bounds__(256) void k_aggregate(
        const unsigned* __restrict__ hb,
        const unsigned* __restrict__ rh, const unsigned* __restrict__ rl,
        const float* __restrict__ bias, const float* __restrict__ gg,
        const float* __restrict__ gb, const float* __restrict__ dinv,
        const int* __restrict__ off, const int* __restrict__ csrc,
        const float* __restrict__ cw,
        unsigned* __restrict__ oh, unsigned* __restrict__ ol) {
    int lane = threadIdx.x & 31;
    int i = blockIdx.x * 8 + (threadIdx.x >> 5);
    float di = dinv[i];
    float sw = di * di;

    float a[8];
    {
        uint4 hv = ((const uint4*)(hb + (size_t)i * 128))[lane];
        float2 f0 = upkb(hv.x), f1 = upkb(hv.y), f2 = upkb(hv.z), f3 = upkb(hv.w);
        a[0] = f0.x * sw; a[1] = f0.y * sw;
        a[2] = f1.x * sw; a[3] = f1.y * sw;
        a[4] = f2.x * sw; a[5] = f2.y * sw;
        a[6] = f3.x * sw; a[7] = f3.y * sw;
    }

    int beg = off[i], end = off[i + 1];
    for (int e0 = beg; e0 < end; e0 += 32) {
        int n = min(32, end - e0);
        int sl = 0; float wl = 0.0f;
        if (lane < n) { sl = csrc[e0 + lane]; wl = cw[e0 + lane]; }
        int j = 0;
        for (; j + 4 <= n; j += 4) {
            int s0j = __shfl_sync(~0u, sl, j);
            int s1j = __shfl_sync(~0u, sl, j + 1);
            int s2j = __shfl_sync(~0u, sl, j + 2);
            int s3j = __shfl_sync(~0u, sl, j + 3);
            float w0j = __shfl_sync(~0u, wl, j);
            float w1j = __shfl_sync(~0u, wl, j + 1);
            float w2j = __shfl_sync(~0u, wl, j + 2);
            float w3j = __shfl_sync(~0u, wl, j + 3);
            uint4 u0 = ((const uint4*)(hb + (size_t)s0j * 128))[lane];
            uint4 u1 = ((const uint4*)(hb + (size_t)s1j * 128))[lane];
            uint4 u2 = ((const uint4*)(hb + (size_t)s2j * 128))[lane];
            uint4 u3 = ((const uint4*)(hb + (size_t)s3j * 128))[lane];
            EDGE_FMA8(u0, w0j);
            EDGE_FMA8(u1, w1j);
            EDGE_FMA8(u2, w2j);
            EDGE_FMA8(u3, w3j);
        }
        for (; j < n; j++) {
            int sj = __shfl_sync(~0u, sl, j);
            float wj = __shfl_sync(~0u, wl, j);
            uint4 u = ((const uint4*)(hb + (size_t)sj * 128))[lane];
            EDGE_FMA8(u, wj);
        }
    }

    const float4* b4 = (const float4*)bias;
    float4 bb0 = b4[lane * 2], bb1 = b4[lane * 2 + 1];
    a[0] += bb0.x; a[1] += bb0.y; a[2] += bb0.z; a[3] += bb0.w;
    a[4] += bb1.x; a[5] += bb1.y; a[6] += bb1.z; a[7] += bb1.w;

    float s1 = 0.0f, s2 = 0.0f;
    #pragma unroll
    for (int k = 0; k < 8; k++) { s1 += a[k]; s2 += a[k] * a[k]; }
    float mu, inv;
    warp_gn(s1, s2, mu, inv);

    const float4* g4 = (const float4*)gg;
    const float4* e4 = (const float4*)gb;
    float4 gA = g4[lane * 2], gB = g4[lane * 2 + 1];
    float4 eA = e4[lane * 2], eB = e4[lane * 2 + 1];

    uint4 hh = ((const uint4*)(rh + (size_t)i * 128))[lane];
    uint4 ll = ((const uint4*)(rl + (size_t)i * 128))[lane];
    float2 x01 = upk2(hh.x, ll.x), x23 = upk2(hh.y, ll.y);
    float2 x45 = upk2(hh.z, ll.z), x67 = upk2(hh.w, ll.w);

    float r[8];
    r[0] = fmaxf((a[0] - mu) * inv * gA.x + eA.x, 0.0f) + x01.x;
    r[1] = fmaxf((a[1] - mu) * inv * gA.y + eA.y, 0.0f) + x01.y;
    r[2] = fmaxf((a[2] - mu) * inv * gA.z + eA.z, 0.0f) + x23.x;
    r[3] = fmaxf((a[3] - mu) * inv * gA.w + eA.w, 0.0f) + x23.y;
    r[4] = fmaxf((a[4] - mu) * inv * gB.x + eB.x, 0.0f) + x45.x;
    r[5] = fmaxf((a[5] - mu) * inv * gB.y + eB.y, 0.0f) + x45.y;
    r[6] = fmaxf((a[6] - mu) * inv * gB.z + eB.z, 0.0f) + x67.x;
    r[7] = fmaxf((a[7] - mu) * inv * gB.w + eB.w, 0.0f) + x67.y;

    if (ol != nullptr) {
        // hi + lo output (feeds next GEMM)
        float lx, ly;
        uint4 ov, lv;
        ov.x = pack_hi2(r[0], r[1], lx, ly); lv.x = pack2(lx, ly);
        ov.y = pack_hi2(r[2], r[3], lx, ly); lv.y = pack2(lx, ly);
        ov.z = pack_hi2(r[4], r[5], lx, ly); lv.z = pack2(lx, ly);
        ov.w = pack_hi2(r[6], r[7], lx, ly); lv.w = pack2(lx, ly);
        ((uint4*)(oh + (size_t)i * 128))[lane] = ov;
        ((uint4*)(ol + (size_t)i * 128))[lane] = lv;
    } else {
        // hi-only output (feeds pooling)
        uint4 ov;
        ov.x = pack2(r[0], r[1]);
        ov.y = pack2(r[2], r[3]);
        ov.z = pack2(r[4], r[5]);
        ov.w = pack2(r[6], r[7]);
        ((uint4*)(oh + (size_t)i * 128))[lane] = ov;
    }
}

// ---------------- pooling: bf16 input, register run-accumulate ----------------
#define PCH 512
__global__ __launch_bounds__(128) void k_pool(
        const unsigned* __restrict__ xb, const int* __restrict__ batch,
        float* pool, float* cnt) {
    int c = threadIdx.x;                 // uint index 0..127 (2 channels)
    int base = blockIdx.x * PCH;
    int end = min(base + PCH, N_NODES);
    if (base >= end) return;
    int curg = __ldg(batch + base);
    float r0 = 0.0f, r1 = 0.0f;
    int run = 0;
    for (int i = base; i < end; i++) {
        int g = __ldg(batch + i);
        if (g != curg) {                 // uniform across block (batch sorted)
            atomicAdd(&pool[curg * HID + 2 * c], r0);
            atomicAdd(&pool[curg * HID + 2 * c + 1], r1);
            if (c == 0) atomicAdd(&cnt[curg], (float)run);
            r0 = r1 = 0.0f; run = 0; curg = g;
        }
        float2 f = upkb(__ldg(xb + (size_t)i * 128 + c));
        r0 += f.x; r1 += f.y; run++;
    }
    atomicAdd(&pool[curg * HID + 2 * c], r0);
    atomicAdd(&pool[curg * HID + 2 * c + 1], r1);
    if (c == 0) atomicAdd(&cnt[curg], (float)run);
}

// ---------------- final MLP ----------------
__device__ __forceinline__ void gn_stats_blk(float v, float* r1, float* r2, int c,
                                             float& mu, float& inv) {
    r1[c] = v; r2[c] = v * v;
    __syncthreads();
    #pragma unroll
    for (int s = 128; s > 0; s >>= 1) {
        if (c < s) { r1[c] += r1[c + s]; r2[c] += r2[c + s]; }
        __syncthreads();
    }
    mu = r1[0] * (1.0f / HID);
    float var = r2[0] * (1.0f / HID) - mu * mu;
    inv = rsqrtf(fmaxf(var, 0.0f) + EPS);
    __syncthreads();
}

__global__ void k_final(const float* __restrict__ pool, const float* __restrict__ cnt,
                        const float* __restrict__ W1, const float* __restrict__ b1,
                        const float* __restrict__ g, const float* __restrict__ be,
                        const float* __restrict__ W2, const float* __restrict__ b2,
                        float* __restrict__ out) {
    __shared__ float p[HID];
    __shared__ float hs[HID];
    __shared__ float r1[HID], r2[HID];
    int gi = blockIdx.x, c = threadIdx.x;
    float cc = fmaxf(cnt[gi], 1.0f);
    p[c] = pool[gi * HID + c] / cc;
    __syncthreads();
    float v = b1[c];
    #pragma unroll 8
    for (int k = 0; k < HID; k++) v = fmaf(p[k], W1[k * HID + c], v);
    v = fmaxf(v, 0.0f);
    float mu, inv;
    gn_stats_blk(v, r1, r2, c, mu, inv);
    hs[c] = (v - mu) * inv * g[c] + be[c];
    __syncthreads();
    if (c < ZDIM) {
        float o = b2[c];
        #pragma unroll 8
        for (int k = 0; k < HID; k++) o = fmaf(hs[k], W2[k * ZDIM + c], o);
        out[gi * ZDIM + c] = o;
    }
}

// ---------------- host launch ----------------
extern "C" void kernel_launch(void* const* d_in, const int* in_sizes, int n_in,
                              void* d_out, int out_size) {
    const float* voxel_pos = (const float*)d_in[0];
    const int*   edges     = (const int*)d_in[1];
    const int*   batch     = (const int*)d_in[2];
    const float* W_in      = (const float*)d_in[3];
    const float* b_in      = (const float*)d_in[4];
    const float* g_in      = (const float*)d_in[5];
    const float* be_in     = (const float*)d_in[6];
    const float* conv_W    = (const float*)d_in[7];
    const float* conv_b    = (const float*)d_in[8];
    const float* gn_g      = (const float*)d_in[9];
    const float* gn_b      = (const float*)d_in[10];
    const float* W_o1      = (const float*)d_in[11];
    const float* b_o1      = (const float*)d_in[12];
    const float* g_o       = (const float*)d_in[13];
    const float* be_o      = (const float*)d_in[14];
    const float* W_o2      = (const float*)d_in[15];
    const float* b_o2      = (const float*)d_in[16];
    float* out = (float*)d_out;

    const int* src = edges;
    const int* dst = edges + N_EDGES;

    float *deg, *dinv, *cw, *pool, *cnt;
    int *off, *cursor, *csrc, *bsum;
    unsigned *hbuf, *xh, *xl, *yh, *yl, *wh, *wl;
    cudaGetSymbolAddress((void**)&deg, g_deg);
    cudaGetSymbolAddress((void**)&dinv, g_dinv);
    cudaGetSymbolAddress((void**)&off, g_off);
    cudaGetSymbolAddress((void**)&cursor, g_cursor);
    cudaGetSymbolAddress((void**)&csrc, g_csrc);
    cudaGetSymbolAddress((void**)&cw, g_cw);
    cudaGetSymbolAddress((void**)&hbuf, g_h);
    cudaGetSymbolAddress((void**)&pool, g_pool);
    cudaGetSymbolAddress((void**)&cnt, g_cnt);
    cudaGetSymbolAddress((void**)&bsum, g_bsum);
    cudaGetSymbolAddress((void**)&xh, g_xh);
    cudaGetSymbolAddress((void**)&xl, g_xl);
    cudaGetSymbolAddress((void**)&yh, g_yh);
    cudaGetSymbolAddress((void**)&yl, g_yl);
    cudaGetSymbolAddress((void**)&wh, g_wh);
    cudaGetSymbolAddress((void**)&wl, g_wl);

    cudaFuncSetAttribute(k_gemm_bf, cudaFuncAttributeMaxDynamicSharedMemorySize, GSMEM);

    int nb_edges = (N_EDGES + 255) / 256;
    dim3 ggrid((N_NODES + 127) / 128, 2);
    int agrid = N_NODES / 8;

    // 1: merged setup (inproj | wsplit | deg/cursor init | pool zero)
    k_setup<<<NB_SETUP, 256>>>(voxel_pos, W_in, b_in, g_in, be_in, xh, xl,
                               conv_W, wh, wl, deg, cursor, pool, cnt);
    k_gemm_bf<<<ggrid, 256, GSMEM>>>(xh, xl, wh, wl, hbuf, N_NODES);         // 2
    k_deg<<<nb_edges, 256>>>(dst, deg);                                      // 3
    k_bsum2<<<SCAN_NB, SCAN_B>>>(deg, dinv, bsum);                           // 4
    k_scan2<<<SCAN_NB, SCAN_B>>>(deg, bsum, off);                            // 5
    k_csr<<<nb_edges, 256>>>(src, dst, dinv, off, cursor, csrc, cw);         // 6

    // layer 0
    k_aggregate<<<agrid, 256>>>(hbuf, xh, xl, conv_b + 0 * HID, gn_g + 0 * HID,
                                gn_b + 0 * HID, dinv, off, csrc, cw, yh, yl);
    // layer 1
    k_gemm_bf<<<ggrid, 256, GSMEM>>>(yh, yl, wh + 1 * 256 * 128,
                                     wl + 1 * 256 * 128, hbuf, N_NODES);
    k_aggregate<<<agrid, 256>>>(hbuf, yh, yl, conv_b + 1 * HID, gn_g + 1 * HID,
                                gn_b + 1 * HID, dinv, off, csrc, cw, xh, xl);
    // layer 2 -> bf16 hi only (feeds pooling)
    k_gemm_bf<<<ggrid, 256, GSMEM>>>(xh, xl, wh + 2 * 256 * 128,
                                     wl + 2 * 256 * 128, hbuf, N_NODES);
    k_aggregate<<<agrid, 256>>>(hbuf, xh, xl, conv_b + 2 * HID, gn_g + 2 * HID,
                                gn_b + 2 * HID, dinv, off, csrc, cw,
                                yh, (unsigned*)nullptr);

    k_pool<<<(N_NODES + PCH - 1) / PCH, 128>>>(yh, batch, pool, cnt);
    k_final<<<NGRAPHS, HID>>>(pool, cnt, W_o1, b_o1, g_o, be_o, W_o2, b_o2, out);
}

// round 15
// speedup vs baseline: 1.0486x; 1.0486x over previous
#include <cuda_runtime.h>
#include <cuda_bf16.h>
#include <cstdint>

#define N_NODES 50000
#define N_EDGES 300000
#define HID 256
#define ZDIM 128
#define NLAYERS 3
#define NGRAPHS 16
#define EPS 1e-5f

// ---------------- device scratch (no allocations allowed) ----------------
__device__ float g_deg[N_NODES];
__device__ float g_dinv[N_NODES];
__device__ int   g_off[N_NODES + 1];
__device__ int   g_cursor[N_NODES];
__device__ int   g_csrc[N_EDGES];
__device__ float g_cw[N_EDGES];
__device__ float g_y[N_NODES * HID];
__device__ unsigned g_h[N_NODES * 128];    // h as bf16x2: 128 uints per row (256 ch)
__device__ unsigned g_xh[N_NODES * 128];   // bf16x2 hi
__device__ unsigned g_xl[N_NODES * 128];   // bf16x2 lo
__device__ unsigned g_yh[N_NODES * 128];
__device__ unsigned g_yl[N_NODES * 128];
__device__ unsigned g_wh[NLAYERS * 256 * 128];  // W^T split hi: [l][n][kpair]
__device__ unsigned g_wl[NLAYERS * 256 * 128];
__device__ float g_pool[NGRAPHS * HID];
__device__ float g_cnt[NGRAPHS];
__device__ int   g_bsum[64];

// ---------------- bf16 helpers ----------------
__device__ __forceinline__ unsigned pack_hi2(float x, float y, float& lx, float& ly) {
    __nv_bfloat162 h = __floats2bfloat162_rn(x, y);
    lx = x - __bfloat162float(h.x);
    ly = y - __bfloat162float(h.y);
    unsigned u;
    *reinterpret_cast<__nv_bfloat162*>(&u) = h;
    return u;
}
__device__ __forceinline__ unsigned pack2(float x, float y) {
    __nv_bfloat162 h = __floats2bfloat162_rn(x, y);
    unsigned u;
    *reinterpret_cast<__nv_bfloat162*>(&u) = h;
    return u;
}
__device__ __forceinline__ float2 upkb(unsigned u) {
    return __bfloat1622float2(*reinterpret_cast<__nv_bfloat162*>(&u));
}
__device__ __forceinline__ float2 upk2(unsigned uh, unsigned ul) {
    float2 a = upkb(uh), b = upkb(ul);
    return make_float2(a.x + b.x, a.y + b.y);
}

__device__ __forceinline__ uint32_t smem_u32(const void* p) {
    uint32_t a;
    asm("{ .reg .u64 t; cvta.to.shared.u64 t, %1; cvt.u32.u64 %0, t; }" : "=r"(a) : "l"(p));
    return a;
}

// ---------------- warp GroupNorm helper ----------------
__device__ __forceinline__ void warp_gn(float s1, float s2, float& mu, float& inv) {
    #pragma unroll
    for (int s = 16; s > 0; s >>= 1) {
        s1 += __shfl_xor_sync(~0u, s1, s);
        s2 += __shfl_xor_sync(~0u, s2, s);
    }
    mu = s1 * (1.0f / HID);
    float var = s2 * (1.0f / HID) - mu * mu;
    inv = rsqrtf(fmaxf(var, 0.0f) + EPS);
}

// ------- merged setup: inproj | wsplit | deg/cursor init | pool zero -------
#define NB_INPROJ (N_NODES / 8)
#define NB_WSPLIT ((NLAYERS * 256 * 128) / 256)
#define NB_INIT   ((N_NODES + 255) / 256)
#define NB_SETUP  (NB_INPROJ + NB_WSPLIT + NB_INIT + 1)

__global__ __launch_bounds__(256) void k_setup(
        const float* __restrict__ pos, const float* __restrict__ W,
        const float* __restrict__ b, const float* __restrict__ g,
        const float* __restrict__ be,
        unsigned* __restrict__ oh, unsigned* __restrict__ ol,
        const float* __restrict__ convW, unsigned* __restrict__ Bh,
        unsigned* __restrict__ Bl,
        float* __restrict__ deg, int* __restrict__ cursor,
        float* __restrict__ pool, float* __restrict__ cnt) {
    int blk = blockIdx.x;
    if (blk < NB_INPROJ) {
        // ---- input projection: warp per node ----
        int lane = threadIdx.x & 31;
        int i = blk * 8 + (threadIdx.x >> 5);
        float px = pos[i * 3 + 0], py = pos[i * 3 + 1], pz = pos[i * 3 + 2];
        const float4* W0 = (const float4*)W;
        const float4* W1 = (const float4*)(W + HID);
        const float4* W2 = (const float4*)(W + 2 * HID);
        const float4* b4 = (const float4*)b;
        float4 v[2];
        float s1 = 0.0f, s2 = 0.0f;
        #pragma unroll
        for (int q = 0; q < 2; q++) {
            int c4 = lane + q * 32;
            float4 w0 = W0[c4], w1 = W1[c4], w2 = W2[c4], bb = b4[c4];
            float4 r;
            r.x = fmaxf(fmaf(px, w0.x, fmaf(py, w1.x, fmaf(pz, w2.x, bb.x))), 0.0f);
            r.y = fmaxf(fmaf(px, w0.y, fmaf(py, w1.y, fmaf(pz, w2.y, bb.y))), 0.0f);
            r.z = fmaxf(fmaf(px, w0.z, fmaf(py, w1.z, fmaf(pz, w2.z, bb.z))), 0.0f);
            r.w = fmaxf(fmaf(px, w0.w, fmaf(py, w1.w, fmaf(pz, w2.w, bb.w))), 0.0f);
            s1 += r.x + r.y + r.z + r.w;
            s2 += r.x * r.x + r.y * r.y + r.z * r.z + r.w * r.w;
            v[q] = r;
        }
        float mu, inv;
        warp_gn(s1, s2, mu, inv);
        const float4* g4 = (const float4*)g;
        const float4* be4 = (const float4*)be;
        unsigned* ohp = oh + (size_t)i * 128;
        unsigned* olp = ol + (size_t)i * 128;
        #pragma unroll
        for (int q = 0; q < 2; q++) {
            int c4 = lane + q * 32;
            float4 gg = g4[c4], ee = be4[c4], r = v[q];
            r.x = (r.x - mu) * inv * gg.x + ee.x;
            r.y = (r.y - mu) * inv * gg.y + ee.y;
            r.z = (r.z - mu) * inv * gg.z + ee.z;
            r.w = (r.w - mu) * inv * gg.w + ee.w;
            float lx, ly;
            ohp[c4 * 2]     = pack_hi2(r.x, r.y, lx, ly);
            olp[c4 * 2]     = pack2(lx, ly);
            ohp[c4 * 2 + 1] = pack_hi2(r.z, r.w, lx, ly);
            olp[c4 * 2 + 1] = pack2(lx, ly);
        }
    } else if (blk < NB_INPROJ + NB_WSPLIT) {
        // ---- weight transpose + split ----
        int idx = (blk - NB_INPROJ) * 256 + threadIdx.x;
        int ln = idx >> 7, p = idx & 127;
        int l = ln >> 8, n = ln & 255;
        const float* Wl = convW + (size_t)l * 65536;
        float w0 = Wl[(size_t)(2 * p) * 256 + n];
        float w1 = Wl[(size_t)(2 * p + 1) * 256 + n];
        float l0, l1;
        unsigned hi = pack_hi2(w0, w1, l0, l1);
        Bh[(size_t)ln * 128 + p] = hi;
        Bl[(size_t)ln * 128 + p] = pack2(l0, l1);
    } else if (blk < NB_INPROJ + NB_WSPLIT + NB_INIT) {
        // ---- deg/cursor init ----
        int i = (blk - NB_INPROJ - NB_WSPLIT) * 256 + threadIdx.x;
        if (i < N_NODES) { deg[i] = 1.0f; cursor[i] = 0; }
    } else {
        // ---- pool/cnt zero ----
        for (int k = threadIdx.x; k < NGRAPHS * HID; k += 256) pool[k] = 0.0f;
        if (threadIdx.x < NGRAPHS) cnt[threadIdx.x] = 0.0f;
    }
}

// ---------------- degree / CSR build ----------------
__global__ void k_deg(const int* __restrict__ dst, float* deg) {
    int e = blockIdx.x * blockDim.x + threadIdx.x;
    if (e < N_EDGES) atomicAdd(&deg[dst[e]], 1.0f);
}

#define SCAN_B 1024
#define SCAN_NB ((N_NODES + SCAN_B - 1) / SCAN_B)

__global__ void k_bsum2(const float* __restrict__ deg, float* __restrict__ dinv,
                        int* bsum) {
    __shared__ int wsum[32];
    int t = threadIdx.x;
    int i = blockIdx.x * SCAN_B + t;
    int v = 0;
    if (i < N_NODES) {
        float d = deg[i];
        dinv[i] = rsqrtf(d);
        v = (int)d - 1;
    }
    #pragma unroll
    for (int s = 16; s > 0; s >>= 1) v += __shfl_xor_sync(~0u, v, s);
    if ((t & 31) == 0) wsum[t >> 5] = v;
    __syncthreads();
    if (t < 32) {
        int x = wsum[t];
        #pragma unroll
        for (int s = 16; s > 0; s >>= 1) x += __shfl_xor_sync(~0u, x, s);
        if (t == 0) bsum[blockIdx.x] = x;
    }
}

// scan with inlined block-prefix
__global__ void k_scan2(const float* __restrict__ deg, const int* __restrict__ bsum,
                        int* off) {
    __shared__ int wsum[32];
    __shared__ int bpre_s;
    int t = threadIdx.x, lane = t & 31, w = t >> 5;
    if (t < 64) {
        int v = (t < blockIdx.x && t < SCAN_NB) ? bsum[t] : 0;
        #pragma unroll
        for (int s = 16; s > 0; s >>= 1) v += __shfl_xor_sync(~0u, v, s);
        if (t == 0) wsum[30] = v;
        if (t == 32) wsum[31] = v;
    }
    __syncthreads();
    if (t == 0) bpre_s = wsum[30] + wsum[31];
    __syncthreads();

    int i = blockIdx.x * SCAN_B + t;
    int v = (i < N_NODES) ? ((int)deg[i] - 1) : 0;
    int x = v;
    #pragma unroll
    for (int s = 1; s < 32; s <<= 1) {
        int n = __shfl_up_sync(~0u, x, s);
        if (lane >= s) x += n;
    }
    if (lane == 31) wsum[w] = x;
    __syncthreads();
    if (w == 0) {
        int y = wsum[lane];
        #pragma unroll
        for (int s = 1; s < 32; s <<= 1) {
            int n = __shfl_up_sync(~0u, y, s);
            if (lane >= s) y += n;
        }
        wsum[lane] = y;
    }
    __syncthreads();
    int incl = x + ((w > 0) ? wsum[w - 1] : 0);
    if (i < N_NODES) off[i + 1] = bpre_s + incl;
    if (i == 0) off[0] = 0;
}

__global__ void k_csr(const int* __restrict__ src, const int* __restrict__ dst,
                      const float* __restrict__ dinv, const int* __restrict__ off,
                      int* cursor, int* csrc, float* cw) {
    int e = blockIdx.x * blockDim.x + threadIdx.x;
    if (e >= N_EDGES) return;
    int s = src[e], d = dst[e];
    int p = atomicAdd(&cursor[d], 1);
    int idx = off[d] + p;
    csrc[idx] = s;
    cw[idx] = dinv[s] * dinv[d];
}

// ---------------- bf16x3 MMA GEMM: cp.async 3-stage pipeline + ldmatrix ----------------
#define MMA_BF16(d0, d1, d2, d3, a0, a1, a2, a3, b0, b1)                      \
    asm volatile(                                                             \
        "mma.sync.aligned.m16n8k16.row.col.f32.bf16.bf16.f32 "               \
        "{%0,%1,%2,%3}, {%4,%5,%6,%7}, {%8,%9}, {%0,%1,%2,%3};\n"            \
        : "+f"(d0), "+f"(d1), "+f"(d2), "+f"(d3)                              \
        : "r"(a0), "r"(a1), "r"(a2), "r"(a3), "r"(b0), "r"(b1))

#define LDSM_X4(r0, r1, r2, r3, addr)                                         \
    asm volatile("ldmatrix.sync.aligned.m8n8.x4.shared.b16 {%0,%1,%2,%3}, [%4];" \
        : "=r"(r0), "=r"(r1), "=r"(r2), "=r"(r3) : "r"(addr))

#define CP16(dst, src, ssz)                                                   \
    asm volatile("cp.async.cg.shared.global [%0], [%1], 16, %2;"             \
        :: "r"(dst), "l"(src), "r"(ssz))
#define CP_COMMIT() asm volatile("cp.async.commit_group;" ::: "memory")
#define CP_WAIT1() asm volatile("cp.async.wait_group 1;" ::: "memory")
#define CP_WAIT0() asm volatile("cp.async.wait_group 0;" ::: "memory")

#define ARR_B 6144
#define STG_B 24576
#define GSMEM (3 * STG_B)

__global__ void __launch_bounds__(256, 2) k_gemm_bf(
        const unsigned* __restrict__ Agh, const unsigned* __restrict__ Agl,
        const unsigned* __restrict__ Bgh, const unsigned* __restrict__ Bgl,
        unsigned* __restrict__ C, int M) {
    extern __shared__ unsigned smg[];
    uint32_t sb = smem_u32(smg);
    int t = threadIdx.x;
    int lane = t & 31, wid = t >> 5;
    int wm = (wid >> 2) * 64;
    int wn = (wid & 3) * 32;
    int g = lane >> 2, tig = lane & 3;
    int m0 = blockIdx.x * 128, n0 = blockIdx.y * 128;

    float acc[4][4][4];
    #pragma unroll
    for (int mt = 0; mt < 4; mt++)
        #pragma unroll
        for (int nt = 0; nt < 4; nt++)
            #pragma unroll
            for (int r = 0; r < 4; r++) acc[mt][nt][r] = 0.0f;

    int rr = t >> 1, q = t & 1;
    uint32_t a_ok = ((m0 + rr) < M) ? 16u : 0u;
    const char* pAh = (const char*)(Agh + (size_t)(m0 + rr) * 128) + q * 16;
    const char* pAl = (const char*)(Agl + (size_t)(m0 + rr) * 128) + q * 16;
    const char* pBh = (const char*)(Bgh + (size_t)(n0 + rr) * 128) + q * 16;
    const char* pBl = (const char*)(Bgl + (size_t)(n0 + rr) * 128) + q * 16;
    uint32_t sdst = sb + rr * 48 + q * 16;

    uint32_t a_off[4];
    #pragma unroll
    for (int mt = 0; mt < 4; mt++) {
        int row = wm + mt * 16 + (lane & 7) + ((lane >> 3) & 1) * 8;
        a_off[mt] = row * 48 + (lane >> 4) * 16;
    }
    uint32_t b_off[2];
    #pragma unroll
    for (int p = 0; p < 2; p++) {
        int nrow = wn + p * 16 + (lane & 7) + ((lane >> 4) & 1) * 8;
        b_off[p] = nrow * 48 + ((lane >> 3) & 1) * 16;
    }

    #define ISSUE(kt, stg) do {                                               \
        uint32_t d = sdst + (stg) * STG_B;                                    \
        int ko = (kt) * 32;                                                   \
        CP16(d,               pAh + ko, a_ok);                                \
        CP16(d + ARR_B,       pAl + ko, a_ok);                                \
        CP16(d + 2 * ARR_B,   pBh + ko, 16u);                                 \
        CP16(d + 3 * ARR_B,   pBl + ko, 16u);                                 \
        CP_COMMIT();                                                          \
    } while (0)

    #define COMPUTE(so) do {                                                  \
        unsigned afh[4][4], afl[4][4], bfh[4][2], bfl[4][2];                  \
        uint32_t ahb = sb + (so), alb = ahb + ARR_B;                          \
        uint32_t bhb = ahb + 2 * ARR_B, blb = ahb + 3 * ARR_B;                \
        _Pragma("unroll")                                                     \
        for (int mt = 0; mt < 4; mt++) {                                      \
            LDSM_X4(afh[mt][0], afh[mt][1], afh[mt][2], afh[mt][3], ahb + a_off[mt]); \
            LDSM_X4(afl[mt][0], afl[mt][1], afl[mt][2], afl[mt][3], alb + a_off[mt]); \
        }                                                                     \
        _Pragma("unroll")                                                     \
        for (int p = 0; p < 2; p++) {                                         \
            LDSM_X4(bfh[2*p][0], bfh[2*p][1], bfh[2*p+1][0], bfh[2*p+1][1], bhb + b_off[p]); \
            LDSM_X4(bfl[2*p][0], bfl[2*p][1], bfl[2*p+1][0], bfl[2*p+1][1], blb + b_off[p]); \
        }                                                                     \
        _Pragma("unroll")                                                     \
        for (int mt = 0; mt < 4; mt++)                                        \
            _Pragma("unroll")                                                 \
            for (int nt = 0; nt < 4; nt++) {                                  \
                MMA_BF16(acc[mt][nt][0], acc[mt][nt][1], acc[mt][nt][2], acc[mt][nt][3], \
                         afh[mt][0], afh[mt][1], afh[mt][2], afh[mt][3],      \
                         bfh[nt][0], bfh[nt][1]);                             \
                MMA_BF16(acc[mt][nt][0], acc[mt][nt][1], acc[mt][nt][2], acc[mt][nt][3], \
                         afh[mt][0], afh[mt][1], afh[mt][2], afh[mt][3],      \
                         bfl[nt][0], bfl[nt][1]);                             \
                MMA_BF16(acc[mt][nt][0], acc[mt][nt][1], acc[mt][nt][2], acc[mt][nt][3], \
                         afl[mt][0], afl[mt][1], afl[mt][2], afl[mt][3],      \
                         bfh[nt][0], bfh[nt][1]);                             \
            }                                                                 \
    } while (0)

    ISSUE(0, 0);
    ISSUE(1, 1);

    int cur = 0;
    uint32_t curo = 0;
    #pragma unroll 1
    for (int kt = 0; kt < 15; kt++) {
        CP_WAIT1();
        __syncthreads();
        if (kt < 14) {
            int stg = cur + 2; if (stg >= 3) stg -= 3;
            ISSUE(kt + 2, stg);
        }
        COMPUTE(curo);
        cur++; if (cur == 3) cur = 0;
        curo = cur * STG_B;
    }
    CP_WAIT0();
    __syncthreads();
    COMPUTE(curo);

    #pragma unroll
    for (int mt = 0; mt < 4; mt++) {
        #pragma unroll
        for (int nt = 0; nt < 4; nt++) {
            int r0 = m0 + wm + mt * 16 + g;
            int ci = (n0 + wn + nt * 8 + tig * 2) >> 1;
            if (r0 < M)
                C[(size_t)r0 * 128 + ci] = pack2(acc[mt][nt][0], acc[mt][nt][1]);
            if (r0 + 8 < M)
                C[(size_t)(r0 + 8) * 128 + ci] = pack2(acc[mt][nt][2], acc[mt][nt][3]);
        }
    }
    #undef ISSUE
    #undef COMPUTE
}

// ---- aggregate: warp per node, bf16 h gather (1 LDG/edge), x4 unroll ----
#define EDGE_FMA8(u, wj) do {                                                 \
    float2 f0 = upkb(u.x), f1 = upkb(u.y), f2 = upkb(u.z), f3 = upkb(u.w);    \
    a[0] = fmaf(f0.x, wj, a[0]); a[1] = fmaf(f0.y, wj, a[1]);                 \
    a[2] = fmaf(f1.x, wj, a[2]); a[3] = fmaf(f1.y, wj, a[3]);                 \
    a[4] = fmaf(f2.x, wj, a[4]); a[5] = fmaf(f2.y, wj, a[5]);                 \
    a[6] = fmaf(f3.x, wj, a[6]); a[7] = fmaf(f3.y, wj, a[7]);                 \
} while (0)

__global__ __launch_bounds__(256) void k_aggregate(
        const unsigned* __restrict__ hb,
        const unsigned* __restrict__ rh, const unsigned* __restrict__ rl,
        const float* __restrict__ bias, const float* __restrict__ gg,
        const float* __restrict__ gb, const float* __restrict__ dinv,
        const int* __restrict__ off, const int* __restrict__ csrc,
        const float* __restrict__ cw,
        float* __restrict__ xout, unsigned* __restrict__ oh,
        unsigned* __restrict__ ol) {
    int lane = threadIdx.x & 31;
    int i = blockIdx.x * 8 + (threadIdx.x >> 5);
    float di = dinv[i];
    float sw = di * di;

    float a[8];
    {
        uint4 hv = ((const uint4*)(hb + (size_t)i * 128))[lane];
        float2 f0 = upkb(hv.x), f1 = upkb(hv.y), f2 = upkb(hv.z), f3 = upkb(hv.w);
        a[0] = f0.x * sw; a[1] = f0.y * sw;
        a[2] = f1.x * sw; a[3] = f1.y * sw;
        a[4] = f2.x * sw; a[5] = f2.y * sw;
        a[6] = f3.x * sw; a[7] = f3.y * sw;
    }

    int beg = off[i], end = off[i + 1];
    for (int e0 = beg; e0 < end; e0 += 32) {
        int n = min(32, end - e0);
        int sl = 0; float wl = 0.0f;
        if (lane < n) { sl = csrc[e0 + lane]; wl = cw[e0 + lane]; }
        int j = 0;
        for (; j + 4 <= n; j += 4) {
            int s0j = __shfl_sync(~0u, sl, j);
            int s1j = __shfl_sync(~0u, sl, j + 1);
            int s2j = __shfl_sync(~0u, sl, j + 2);
            int s3j = __shfl_sync(~0u, sl, j + 3);
            float w0j = __shfl_sync(~0u, wl, j);
            float w1j = __shfl_sync(~0u, wl, j + 1);
            float w2j = __shfl_sync(~0u, wl, j + 2);
            float w3j = __shfl_sync(~0u, wl, j + 3);
            uint4 u0 = ((const uint4*)(hb + (size_t)s0j * 128))[lane];
            uint4 u1 = ((const uint4*)(hb + (size_t)s1j * 128))[lane];
            uint4 u2 = ((const uint4*)(hb + (size_t)s2j * 128))[lane];
            uint4 u3 = ((const uint4*)(hb + (size_t)s3j * 128))[lane];
            EDGE_FMA8(u0, w0j);
            EDGE_FMA8(u1, w1j);
            EDGE_FMA8(u2, w2j);
            EDGE_FMA8(u3, w3j);
        }
        for (; j < n; j++) {
            int sj = __shfl_sync(~0u, sl, j);
            float wj = __shfl_sync(~0u, wl, j);
            uint4 u = ((const uint4*)(hb + (size_t)sj * 128))[lane];
            EDGE_FMA8(u, wj);
        }
    }

    const float4* b4 = (const float4*)bias;
    float4 bb0 = b4[lane * 2], bb1 = b4[lane * 2 + 1];
    a[0] += bb0.x; a[1] += bb0.y; a[2] += bb0.z; a[3] += bb0.w;
    a[4] += bb1.x; a[5] += bb1.y; a[6] += bb1.z; a[7] += bb1.w;

    float s1 = 0.0f, s2 = 0.0f;
    #pragma unroll
    for (int k = 0; k < 8; k++) { s1 += a[k]; s2 += a[k] * a[k]; }
    float mu, inv;
    warp_gn(s1, s2, mu, inv);

    const float4* g4 = (const float4*)gg;
    const float4* e4 = (const float4*)gb;
    float4 gA = g4[lane * 2], gB = g4[lane * 2 + 1];
    float4 eA = e4[lane * 2], eB = e4[lane * 2 + 1];

    uint4 hh = ((const uint4*)(rh + (size_t)i * 128))[lane];
    uint4 ll = ((const uint4*)(rl + (size_t)i * 128))[lane];
    float2 x01 = upk2(hh.x, ll.x), x23 = upk2(hh.y, ll.y);
    float2 x45 = upk2(hh.z, ll.z), x67 = upk2(hh.w, ll.w);

    float r[8];
    r[0] = fmaxf((a[0] - mu) * inv * gA.x + eA.x, 0.0f) + x01.x;
    r[1] = fmaxf((a[1] - mu) * inv * gA.y + eA.y, 0.0f) + x01.y;
    r[2] = fmaxf((a[2] - mu) * inv * gA.z + eA.z, 0.0f) + x23.x;
    r[3] = fmaxf((a[3] - mu) * inv * gA.w + eA.w, 0.0f) + x23.y;
    r[4] = fmaxf((a[4] - mu) * inv * gB.x + eB.x, 0.0f) + x45.x;
    r[5] = fmaxf((a[5] - mu) * inv * gB.y + eB.y, 0.0f) + x45.y;
    r[6] = fmaxf((a[6] - mu) * inv * gB.z + eB.z, 0.0f) + x67.x;
    r[7] = fmaxf((a[7] - mu) * inv * gB.w + eB.w, 0.0f) + x67.y;

    if (oh != nullptr) {
        float lx, ly;
        uint4 ov, lv;
        ov.x = pack_hi2(r[0], r[1], lx, ly); lv.x = pack2(lx, ly);
        ov.y = pack_hi2(r[2], r[3], lx, ly); lv.y = pack2(lx, ly);
        ov.z = pack_hi2(r[4], r[5], lx, ly); lv.z = pack2(lx, ly);
        ov.w = pack_hi2(r[6], r[7], lx, ly); lv.w = pack2(lx, ly);
        ((uint4*)(oh + (size_t)i * 128))[lane] = ov;
        ((uint4*)(ol + (size_t)i * 128))[lane] = lv;
    }
    if (xout != nullptr) {
        float4* o4 = (float4*)(xout + (size_t)i * HID);
        o4[lane * 2]     = make_float4(r[0], r[1], r[2], r[3]);
        o4[lane * 2 + 1] = make_float4(r[4], r[5], r[6], r[7]);
    }
}

// ---------------- pooling (branch-free smem accumulate, R13-proven) ----------
#define PCH 512
__global__ void k_pool(const float* __restrict__ x, const int* __restrict__ batch,
                       float* pool, float* cnt) {
    __shared__ float acc[NGRAPHS * HID];
    __shared__ int scnt[NGRAPHS];
    int c = threadIdx.x;
    for (int g = 0; g < NGRAPHS; g++) acc[g * HID + c] = 0.0f;
    if (c < NGRAPHS) scnt[c] = 0;
    __syncthreads();
    int base = blockIdx.x * PCH;
    int end = min(base + PCH, N_NODES);
    for (int i = base; i < end; i++) {
        int g = batch[i];
        acc[g * HID + c] += x[(size_t)i * HID + c];
        if (c == 0) scnt[g]++;
    }
    __syncthreads();
    for (int g = 0; g < NGRAPHS; g++) atomicAdd(&pool[g * HID + c], acc[g * HID + c]);
    if (c < NGRAPHS) atomicAdd(&cnt[c], (float)scnt[c]);
}

// ---------------- final MLP ----------------
__device__ __forceinline__ void gn_stats_blk(float v, float* r1, float* r2, int c,
                                             float& mu, float& inv) {
    r1[c] = v; r2[c] = v * v;
    __syncthreads();
    #pragma unroll
    for (int s = 128; s > 0; s >>= 1) {
        if (c < s) { r1[c] += r1[c + s]; r2[c] += r2[c + s]; }
        __syncthreads();
    }
    mu = r1[0] * (1.0f / HID);
    float var = r2[0] * (1.0f / HID) - mu * mu;
    inv = rsqrtf(fmaxf(var, 0.0f) + EPS);
    __syncthreads();
}

__global__ void k_final(const float* __restrict__ pool, const float* __restrict__ cnt,
                        const float* __restrict__ W1, const float* __restrict__ b1,
                        const float* __restrict__ g, const float* __restrict__ be,
                        const float* __restrict__ W2, const float* __restrict__ b2,
                        float* __restrict__ out) {
    __shared__ float p[HID];
    __shared__ float hs[HID];
    __shared__ float r1[HID], r2[HID];
    int gi = blockIdx.x, c = threadIdx.x;
    float cc = fmaxf(cnt[gi], 1.0f);
    p[c] = pool[gi * HID + c] / cc;
    __syncthreads();
    float v = b1[c];
    #pragma unroll 8
    for (int k = 0; k < HID; k++) v = fmaf(p[k], W1[k * HID + c], v);
    v = fmaxf(v, 0.0f);
    float mu, inv;
    gn_stats_blk(v, r1, r2, c, mu, inv);
    hs[c] = (v - mu) * inv * g[c] + be[c];
    __syncthreads();
    if (c < ZDIM) {
        float o = b2[c];
        #pragma unroll 8
        for (int k = 0; k < HID; k++) o = fmaf(hs[k], W2[k * ZDIM + c], o);
        out[gi * ZDIM + c] = o;
    }
}

// ---------------- host launch ----------------
extern "C" void kernel_launch(void* const* d_in, const int* in_sizes, int n_in,
                              void* d_out, int out_size) {
    const float* voxel_pos = (const float*)d_in[0];
    const int*   edges     = (const int*)d_in[1];
    const int*   batch     = (const int*)d_in[2];
    const float* W_in      = (const float*)d_in[3];
    const float* b_in      = (const float*)d_in[4];
    const float* g_in      = (const float*)d_in[5];
    const float* be_in     = (const float*)d_in[6];
    const float* conv_W    = (const float*)d_in[7];
    const float* conv_b    = (const float*)d_in[8];
    const float* gn_g      = (const float*)d_in[9];
    const float* gn_b      = (const float*)d_in[10];
    const float* W_o1      = (const float*)d_in[11];
    const float* b_o1      = (const float*)d_in[12];
    const float* g_o       = (const float*)d_in[13];
    const float* be_o      = (const float*)d_in[14];
    const float* W_o2      = (const float*)d_in[15];
    const float* b_o2      = (const float*)d_in[16];
    float* out = (float*)d_out;

    const int* src = edges;
    const int* dst = edges + N_EDGES;

    float *deg, *dinv, *cw, *ybuf, *pool, *cnt;
    int *off, *cursor, *csrc, *bsum;
    unsigned *hbuf, *xh, *xl, *yh, *yl, *wh, *wl;
    cudaGetSymbolAddress((void**)&deg, g_deg);
    cudaGetSymbolAddress((void**)&dinv, g_dinv);
    cudaGetSymbolAddress((void**)&off, g_off);
    cudaGetSymbolAddress((void**)&cursor, g_cursor);
    cudaGetSymbolAddress((void**)&csrc, g_csrc);
    cudaGetSymbolAddress((void**)&cw, g_cw);
    cudaGetSymbolAddress((void**)&ybuf, g_y);
    cudaGetSymbolAddress((void**)&hbuf, g_h);
    cudaGetSymbolAddress((void**)&pool, g_pool);
    cudaGetSymbolAddress((void**)&cnt, g_cnt);
    cudaGetSymbolAddress((void**)&bsum, g_bsum);
    cudaGetSymbolAddress((void**)&xh, g_xh);
    cudaGetSymbolAddress((void**)&xl, g_xl);
    cudaGetSymbolAddress((void**)&yh, g_yh);
    cudaGetSymbolAddress((void**)&yl, g_yl);
    cudaGetSymbolAddress((void**)&wh, g_wh);
    cudaGetSymbolAddress((void**)&wl, g_wl);

    cudaFuncSetAttribute(k_gemm_bf, cudaFuncAttributeMaxDynamicSharedMemorySize, GSMEM);

    int nb_edges = (N_EDGES + 255) / 256;
    dim3 ggrid((N_NODES + 127) / 128, 2);
    int agrid = N_NODES / 8;

    // 1: merged setup (inproj | wsplit | deg/cursor init | pool zero)
    k_setup<<<NB_SETUP, 256>>>(voxel_pos, W_in, b_in, g_in, be_in, xh, xl,
                               conv_W, wh, wl, deg, cursor, pool, cnt);
    k_gemm_bf<<<ggrid, 256, GSMEM>>>(xh, xl, wh, wl, hbuf, N_NODES);         // 2
    k_deg<<<nb_edges, 256>>>(dst, deg);                                      // 3
    k_bsum2<<<SCAN_NB, SCAN_B>>>(deg, dinv, bsum);                           // 4
    k_scan2<<<SCAN_NB, SCAN_B>>>(deg, bsum, off);                            // 5
    k_csr<<<nb_edges, 256>>>(src, dst, dinv, off, cursor, csrc, cw);         // 6

    // layer 0
    k_aggregate<<<agrid, 256>>>(hbuf, xh, xl, conv_b + 0 * HID, gn_g + 0 * HID,
                                gn_b + 0 * HID, dinv, off, csrc, cw,
                                (float*)nullptr, yh, yl);
    // layer 1
    k_gemm_bf<<<ggrid, 256, GSMEM>>>(yh, yl, wh + 1 * 256 * 128,
                                     wl + 1 * 256 * 128, hbuf, N_NODES);
    k_aggregate<<<agrid, 256>>>(hbuf, yh, yl, conv_b + 1 * HID, gn_g + 1 * HID,
                                gn_b + 1 * HID, dinv, off, csrc, cw,
                                (float*)nullptr, xh, xl);
    // layer 2 -> fp32 for pooling
    k_gemm_bf<<<ggrid, 256, GSMEM>>>(xh, xl, wh + 2 * 256 * 128,
                                     wl + 2 * 256 * 128, hbuf, N_NODES);
    k_aggregate<<<agrid, 256>>>(hbuf, xh, xl, conv_b + 2 * HID, gn_g + 2 * HID,
                                gn_b + 2 * HID, dinv, off, csrc, cw,
                                ybuf, (unsigned*)nullptr, (unsigned*)nullptr);

    k_pool<<<(N_NODES + PCH - 1) / PCH, HID>>>(ybuf, batch, pool, cnt);
    k_final<<<NGRAPHS, HID>>>(pool, cnt, W_o1, b_o1, g_o, be_o, W_o2, b_o2, out);
}